// round 1
// baseline (speedup 1.0000x reference)
#include <cuda_runtime.h>
#include <math.h>

// Problem constants (fixed for this dataset instance)
#define NG    4096          // groups
#define KPOS  4
#define H     256
#define MNEG  64
#define KDIM  768           // (KPOS-1)*H
#define LDA   1024          // KPOS*H : hist_x[g] = emb[g*LDA .. g*LDA+KDIM)
#define NLOG  65            // 1 positive + MNEG negatives

// Scratch (allocation-free rule: __device__ globals)
__device__ float g_pred[NG * H];    // predicts, 4 MB
__device__ float g_terms[NG];       // per-group (lse - pos_logit)

// ---------------------------------------------------------------------------
// Kernel A: predicts = hist_x @ W + b
// A: emb rows, lda=1024 (only first 768 cols used per group). M=4096,N=256,K=768
// 64x64 tile, BK=16, 256 threads, 4x4 per thread.
// ---------------------------------------------------------------------------
__global__ __launch_bounds__(256) void gemm_kernel(const float* __restrict__ A,
                                                   const float* __restrict__ W,
                                                   const float* __restrict__ bias) {
    __shared__ float As[16][64];   // [k][m]
    __shared__ float Bs[16][64];   // [k][n]
    const int tid = threadIdx.x;
    const int tx  = tid & 15;       // n quad
    const int ty  = tid >> 4;       // m quad
    const int bm0 = blockIdx.y * 64;
    const int bn0 = blockIdx.x * 64;

    // A-tile load mapping: 64 rows x 16 cols, one float4 per thread
    const int arow = tid >> 2;
    const int acol = (tid & 3) * 4;
    // B-tile load mapping: 16 rows x 64 cols, one float4 per thread
    const int brow = tid >> 4;
    const int bcol = (tid & 15) * 4;

    const float* Aptr = A + (size_t)(bm0 + arow) * LDA + acol;
    const float* Wptr = W + (size_t)brow * H + bn0 + bcol;

    float acc[4][4] = {};

    for (int k0 = 0; k0 < KDIM; k0 += 16) {
        float4 av = *(const float4*)(Aptr + k0);
        float4 bv = *(const float4*)(Wptr + (size_t)k0 * H);
        As[acol + 0][arow] = av.x;
        As[acol + 1][arow] = av.y;
        As[acol + 2][arow] = av.z;
        As[acol + 3][arow] = av.w;
        *(float4*)&Bs[brow][bcol] = bv;
        __syncthreads();
#pragma unroll
        for (int kk = 0; kk < 16; kk++) {
            float4 a = *(const float4*)&As[kk][ty * 4];
            float4 w = *(const float4*)&Bs[kk][tx * 4];
            acc[0][0] += a.x * w.x; acc[0][1] += a.x * w.y; acc[0][2] += a.x * w.z; acc[0][3] += a.x * w.w;
            acc[1][0] += a.y * w.x; acc[1][1] += a.y * w.y; acc[1][2] += a.y * w.z; acc[1][3] += a.y * w.w;
            acc[2][0] += a.z * w.x; acc[2][1] += a.z * w.y; acc[2][2] += a.z * w.z; acc[2][3] += a.z * w.w;
            acc[3][0] += a.w * w.x; acc[3][1] += a.w * w.y; acc[3][2] += a.w * w.z; acc[3][3] += a.w * w.w;
        }
        __syncthreads();
    }

    float4 bb = *(const float4*)(bias + bn0 + tx * 4);
#pragma unroll
    for (int i = 0; i < 4; i++) {
        float4 out;
        out.x = acc[i][0] + bb.x;
        out.y = acc[i][1] + bb.y;
        out.z = acc[i][2] + bb.z;
        out.w = acc[i][3] + bb.w;
        *(float4*)&g_pred[(size_t)(bm0 + ty * 4 + i) * H + bn0 + tx * 4] = out;
    }
}

// ---------------------------------------------------------------------------
// Kernel B: per-group logits + log-softmax term
// One block (256 thr = 8 warps) per group. Logit 0 = positive (row 4g+3),
// logits 1..64 = negatives; neg row = p + (p >= 4g ? 4 : 0), p = perm[g][j].
// ---------------------------------------------------------------------------
__global__ __launch_bounds__(256) void loss_kernel(const float* __restrict__ emb,
                                                   const int* __restrict__ perm) {
    const int g    = blockIdx.x;
    const int tid  = threadIdx.x;
    const int warp = tid >> 5;
    const int lane = tid & 31;

    __shared__ float s_pred[H];
    __shared__ float s_logits[NLOG];

    s_pred[tid] = g_pred[(size_t)g * H + tid];
    __syncthreads();

    const float4* p4 = (const float4*)s_pred;
    const float4 pa = p4[lane];
    const float4 pb = p4[lane + 32];

    for (int j = warp; j < NLOG; j += 8) {
        int row;
        if (j == 0) {
            row = 4 * g + 3;
        } else {
            int p = perm[(size_t)g * MNEG + (j - 1)];
            row = p + ((p >= 4 * g) ? 4 : 0);
        }
        const float4* e4 = (const float4*)(emb + (size_t)row * H);
        float4 ea = e4[lane];
        float4 eb = e4[lane + 32];
        float s = ea.x * pa.x + ea.y * pa.y + ea.z * pa.z + ea.w * pa.w
                + eb.x * pb.x + eb.y * pb.y + eb.z * pb.z + eb.w * pb.w;
#pragma unroll
        for (int off = 16; off > 0; off >>= 1)
            s += __shfl_down_sync(0xffffffffu, s, off);
        if (lane == 0) s_logits[j] = s;
    }
    __syncthreads();

    if (warp == 0) {
        // 65 logits: lane handles {lane, lane+32}, lane 0 also handles 64
        float v0 = s_logits[lane];
        float v1 = s_logits[lane + 32];
        float v2 = (lane == 0) ? s_logits[64] : -INFINITY;
        float m = fmaxf(fmaxf(v0, v1), v2);
#pragma unroll
        for (int off = 16; off > 0; off >>= 1)
            m = fmaxf(m, __shfl_xor_sync(0xffffffffu, m, off));
        float s = expf(v0 - m) + expf(v1 - m) + ((lane == 0) ? expf(v2 - m) : 0.0f);
#pragma unroll
        for (int off = 16; off > 0; off >>= 1)
            s += __shfl_xor_sync(0xffffffffu, s, off);
        float lse = m + logf(s);
        if (lane == 0) g_terms[g] = lse - s_logits[0];
    }
}

// ---------------------------------------------------------------------------
// Kernel C: deterministic reduction  loss = mean(terms)
// ---------------------------------------------------------------------------
__global__ __launch_bounds__(256) void reduce_kernel(float* __restrict__ out) {
    __shared__ float s[256];
    float v = 0.0f;
    for (int i = threadIdx.x; i < NG; i += 256)
        v += g_terms[i];
    s[threadIdx.x] = v;
    __syncthreads();
    for (int st = 128; st > 0; st >>= 1) {
        if (threadIdx.x < st) s[threadIdx.x] += s[threadIdx.x + st];
        __syncthreads();
    }
    if (threadIdx.x == 0) out[0] = s[0] / (float)NG;
}

// ---------------------------------------------------------------------------
extern "C" void kernel_launch(void* const* d_in, const int* in_sizes, int n_in,
                              void* d_out, int out_size) {
    const float* emb  = (const float*)d_in[0];   // (16384, 256) f32
    const float* W    = (const float*)d_in[1];   // (768, 256)  f32
    const float* bias = (const float*)d_in[2];   // (256,)      f32
    // d_in[3] = target (unused: analytic)
    const int* perm   = (const int*)d_in[4];     // (4096, 64) int32

    dim3 ggrid(H / 64, NG / 64);   // (4, 64)
    gemm_kernel<<<ggrid, 256>>>(emb, W, bias);
    loss_kernel<<<NG, 256>>>(emb, perm);
    reduce_kernel<<<1, 256>>>((float*)d_out);
}

// round 2
// speedup vs baseline: 1.5409x; 1.5409x over previous
#include <cuda_runtime.h>
#include <math.h>
#include <stdint.h>

// Problem constants
#define NG    4096
#define KPOS  4
#define H     256
#define MNEG  64
#define KDIM  768           // (KPOS-1)*H
#define LDA   1024          // hist_x[g] = emb[g*LDA .. g*LDA+KDIM)
#define NLOG  65

// Scratch
__device__ float g_pred[NG * H];
__device__ float g_terms[NG];

__device__ __forceinline__ uint32_t f2tf32(float f) {
    uint32_t u;
    asm("cvt.rna.tf32.f32 %0, %1;" : "=r"(u) : "f"(f));
    return u;
}

// ---------------------------------------------------------------------------
// Kernel A: predicts = hist_x @ W + b  via TF32 mma.sync  (M=4096,N=256,K=768)
// BM=64 BN=64 BK=16, 128 threads = 4 warps (2x2), warp tile 32x32.
// ---------------------------------------------------------------------------
#define BM 64
#define BN 64
#define BK 16
#define AS_LD 20     // BK + 4 pad: conflict-free a-fragment lds
#define BS_LD 72     // BN + 8 pad: conflict-free b-fragment lds

__global__ __launch_bounds__(128) void gemm_tc(const float* __restrict__ A,
                                               const float* __restrict__ W,
                                               const float* __restrict__ bias) {
    __shared__ uint32_t As[BM][AS_LD];   // tf32 bits, [m][k]
    __shared__ uint32_t Bs[BK][BS_LD];   // tf32 bits, [k][n]

    const int tid  = threadIdx.x;
    const int warp = tid >> 5;
    const int lane = tid & 31;
    const int wm0  = (warp >> 1) * 32;
    const int wn0  = (warp & 1) * 32;
    const int bm0  = blockIdx.y * BM;
    const int bn0  = blockIdx.x * BN;

    // Global->shared mappings
    const int ar  = tid >> 2;          // A row within tile (0..31), +32 for 2nd
    const int akg = (tid & 3) * 4;     // A k offset {0,4,8,12}
    const int bk  = tid >> 4;          // B k row (0..7), +8 for 2nd
    const int bn4 = (tid & 15) * 4;    // B n offset

    const float* Ap0 = A + (size_t)(bm0 + ar) * LDA + akg;
    const float* Ap1 = Ap0 + 32 * LDA;
    const float* Bp0 = W + (size_t)bk * H + bn0 + bn4;
    const float* Bp1 = Bp0 + 8 * H;

    float c[2][4][4];
#pragma unroll
    for (int i = 0; i < 2; i++)
#pragma unroll
        for (int j = 0; j < 4; j++)
#pragma unroll
            for (int q = 0; q < 4; q++) c[i][j][q] = 0.0f;

    // software pipeline: preload iter 0
    float4 ga0 = *(const float4*)Ap0;
    float4 ga1 = *(const float4*)Ap1;
    float4 gb0 = *(const float4*)Bp0;
    float4 gb1 = *(const float4*)Bp1;

    const int mrow = lane >> 2;   // groupID
    const int kq   = lane & 3;    // threadID in group
    const int ncol = lane >> 2;

    for (int it = 0; it < KDIM / BK; it++) {
        // convert + store current tile
        {
            uint32_t* p = &As[ar][akg];
            p[0] = f2tf32(ga0.x); p[1] = f2tf32(ga0.y); p[2] = f2tf32(ga0.z); p[3] = f2tf32(ga0.w);
            p = &As[ar + 32][akg];
            p[0] = f2tf32(ga1.x); p[1] = f2tf32(ga1.y); p[2] = f2tf32(ga1.z); p[3] = f2tf32(ga1.w);
            p = &Bs[bk][bn4];
            p[0] = f2tf32(gb0.x); p[1] = f2tf32(gb0.y); p[2] = f2tf32(gb0.z); p[3] = f2tf32(gb0.w);
            p = &Bs[bk + 8][bn4];
            p[0] = f2tf32(gb1.x); p[1] = f2tf32(gb1.y); p[2] = f2tf32(gb1.z); p[3] = f2tf32(gb1.w);
        }
        __syncthreads();

        // prefetch next tile (latency overlapped with MMA work below)
        if (it < KDIM / BK - 1) {
            Ap0 += BK; Ap1 += BK; Bp0 += BK * H; Bp1 += BK * H;
            ga0 = *(const float4*)Ap0;
            ga1 = *(const float4*)Ap1;
            gb0 = *(const float4*)Bp0;
            gb1 = *(const float4*)Bp1;
        }

#pragma unroll
        for (int ks = 0; ks < 2; ks++) {       // two k8 steps per BK
            uint32_t a[2][4], b[4][2];
#pragma unroll
            for (int mf = 0; mf < 2; mf++) {
                int m = wm0 + mf * 16 + mrow;
                a[mf][0] = As[m][ks * 8 + kq];
                a[mf][1] = As[m + 8][ks * 8 + kq];
                a[mf][2] = As[m][ks * 8 + kq + 4];
                a[mf][3] = As[m + 8][ks * 8 + kq + 4];
            }
#pragma unroll
            for (int nf = 0; nf < 4; nf++) {
                int n = wn0 + nf * 8 + ncol;
                b[nf][0] = Bs[ks * 8 + kq][n];
                b[nf][1] = Bs[ks * 8 + kq + 4][n];
            }
#pragma unroll
            for (int mf = 0; mf < 2; mf++)
#pragma unroll
                for (int nf = 0; nf < 4; nf++) {
                    asm volatile(
                        "mma.sync.aligned.m16n8k8.row.col.f32.tf32.tf32.f32 "
                        "{%0,%1,%2,%3}, {%4,%5,%6,%7}, {%8,%9}, {%0,%1,%2,%3};"
                        : "+f"(c[mf][nf][0]), "+f"(c[mf][nf][1]),
                          "+f"(c[mf][nf][2]), "+f"(c[mf][nf][3])
                        : "r"(a[mf][0]), "r"(a[mf][1]), "r"(a[mf][2]), "r"(a[mf][3]),
                          "r"(b[nf][0]), "r"(b[nf][1]));
                }
        }
        __syncthreads();
    }

    // epilogue: + bias, write predicts
#pragma unroll
    for (int mf = 0; mf < 2; mf++) {
        int m = bm0 + wm0 + mf * 16 + mrow;
#pragma unroll
        for (int nf = 0; nf < 4; nf++) {
            int n = bn0 + wn0 + nf * 8 + kq * 2;
            float2 bb = *(const float2*)(bias + n);
            float2 o0 = make_float2(c[mf][nf][0] + bb.x, c[mf][nf][1] + bb.y);
            float2 o1 = make_float2(c[mf][nf][2] + bb.x, c[mf][nf][3] + bb.y);
            *(float2*)&g_pred[(size_t)m * H + n] = o0;
            *(float2*)&g_pred[(size_t)(m + 8) * H + n] = o1;
        }
    }
}

// ---------------------------------------------------------------------------
// Kernel B: per-group logits + log-softmax term.
// One block (256 thr = 8 warps) per group. neg row = p + (p >= 4g ? 4 : 0).
// ---------------------------------------------------------------------------
__global__ __launch_bounds__(256) void loss_kernel(const float* __restrict__ emb,
                                                   const int* __restrict__ perm) {
    const int g    = blockIdx.x;
    const int tid  = threadIdx.x;
    const int warp = tid >> 5;
    const int lane = tid & 31;

    __shared__ float s_pred[H];
    __shared__ float s_logits[NLOG];
    __shared__ int   s_row[NLOG];

    s_pred[tid] = g_pred[(size_t)g * H + tid];
    if (tid < MNEG) {
        int p = perm[(size_t)g * MNEG + tid];
        s_row[tid + 1] = p + ((p >= 4 * g) ? 4 : 0);
    }
    if (tid == MNEG) s_row[0] = 4 * g + 3;
    __syncthreads();

    const float4* p4 = (const float4*)s_pred;
    const float4 pa = p4[lane];
    const float4 pb = p4[lane + 32];

    for (int j = warp; j < NLOG; j += 8) {
        const float4* e4 = (const float4*)(emb + (size_t)s_row[j] * H);
        float4 ea = e4[lane];
        float4 eb = e4[lane + 32];
        float s = ea.x * pa.x + ea.y * pa.y + ea.z * pa.z + ea.w * pa.w
                + eb.x * pb.x + eb.y * pb.y + eb.z * pb.z + eb.w * pb.w;
#pragma unroll
        for (int off = 16; off > 0; off >>= 1)
            s += __shfl_down_sync(0xffffffffu, s, off);
        if (lane == 0) s_logits[j] = s;
    }
    __syncthreads();

    if (warp == 0) {
        float v0 = s_logits[lane];
        float v1 = s_logits[lane + 32];
        float v2 = (lane == 0) ? s_logits[64] : -INFINITY;
        float m = fmaxf(fmaxf(v0, v1), v2);
#pragma unroll
        for (int off = 16; off > 0; off >>= 1)
            m = fmaxf(m, __shfl_xor_sync(0xffffffffu, m, off));
        float s = expf(v0 - m) + expf(v1 - m) + ((lane == 0) ? expf(v2 - m) : 0.0f);
#pragma unroll
        for (int off = 16; off > 0; off >>= 1)
            s += __shfl_xor_sync(0xffffffffu, s, off);
        float lse = m + logf(s);
        if (lane == 0) g_terms[g] = lse - s_logits[0];
    }
}

// ---------------------------------------------------------------------------
// Kernel C: deterministic mean
// ---------------------------------------------------------------------------
__global__ __launch_bounds__(256) void reduce_kernel(float* __restrict__ out) {
    __shared__ float s[256];
    float v = 0.0f;
    for (int i = threadIdx.x; i < NG; i += 256)
        v += g_terms[i];
    s[threadIdx.x] = v;
    __syncthreads();
    for (int st = 128; st > 0; st >>= 1) {
        if (threadIdx.x < st) s[threadIdx.x] += s[threadIdx.x + st];
        __syncthreads();
    }
    if (threadIdx.x == 0) out[0] = s[0] / (float)NG;
}

// ---------------------------------------------------------------------------
extern "C" void kernel_launch(void* const* d_in, const int* in_sizes, int n_in,
                              void* d_out, int out_size) {
    const float* emb  = (const float*)d_in[0];   // (16384, 256) f32
    const float* W    = (const float*)d_in[1];   // (768, 256)   f32
    const float* bias = (const float*)d_in[2];   // (256,)       f32
    // d_in[3] = target (analytic, unused)
    const int* perm   = (const int*)d_in[4];     // (4096, 64)   int32

    dim3 ggrid(H / BN, NG / BM);   // (4, 64)
    gemm_tc<<<ggrid, 128>>>(emb, W, bias);
    loss_kernel<<<NG, 256>>>(emb, perm);
    reduce_kernel<<<1, 256>>>((float*)d_out);
}

// round 4
// speedup vs baseline: 1.7422x; 1.1307x over previous
#include <cuda_runtime.h>
#include <math.h>
#include <stdint.h>

// Problem constants
#define NG    4096
#define KPOS  4
#define H     256
#define MNEG  64
#define KDIM  768           // (KPOS-1)*H
#define LDA   1024          // hist_x[g] = emb[g*LDA .. g*LDA+KDIM)
#define NLOG  65

// Scratch
__device__ float g_pred[NG * H];
__device__ float g_terms[NG];

// ---------------------------------------------------------------------------
// Kernel A: predicts = hist_x @ W + b  (M=4096, N=256, K=768), TF32 mma.sync
// BM=64 BN=64 BK=16, 256 threads = 8 warps.
// Warp split-K: warps 0-3 handle k[0:8), warps 4-7 handle k[8:16) per tile;
// both use 32x32 warp tiles over the same 64x64 block tile, partial sums
// reduced through smem in the epilogue.
// cp.async 3-stage pipeline, raw fp32 fed to mma.tf32 (truncation).
// ---------------------------------------------------------------------------
#define BM 64
#define BN 64
#define BK 16
#define STAGES 3
#define ITERS  (KDIM / BK)          // 48
#define A_STRIDE 20                 // BK + 4 pad (conflict-free frag LDS)
#define B_STRIDE 72                 // BN + 8 pad (conflict-free frag LDS)
#define A_STAGE_WORDS (BM * A_STRIDE)               // 1280
#define B_STAGE_WORDS (BK * B_STRIDE)               // 1152
#define STAGE_WORDS   (A_STAGE_WORDS + B_STAGE_WORDS)  // 2432 (9728 B)

__device__ __forceinline__ void cp16(float* dst_smem, const float* src) {
    uint32_t d = (uint32_t)__cvta_generic_to_shared(dst_smem);
    asm volatile("cp.async.cg.shared.global [%0], [%1], 16;\n" :: "r"(d), "l"(src));
}

__global__ __launch_bounds__(256) void gemm_tc(const float* __restrict__ A,
                                               const float* __restrict__ W,
                                               const float* __restrict__ bias) {
    // pipeline smem (29184 B), reused as 16 KB reduction buffer in epilogue
    __shared__ __align__(16) float smem[STAGES * STAGE_WORDS];

    const int tid  = threadIdx.x;
    const int warp = tid >> 5;
    const int lane = tid & 31;
    const int kg   = warp >> 2;          // k-group: 0 or 1
    const int wq   = warp & 3;           // warp position in 2x2
    const int wm0  = (wq >> 1) * 32;
    const int wn0  = (wq & 1) * 32;
    const int bm0  = blockIdx.y * BM;
    const int bn0  = blockIdx.x * BN;

    const int mrow = lane >> 2;          // mma groupID
    const int kq   = lane & 3;           // mma threadID-in-group
    const int kb   = kg * 8;             // this warp's k-offset within BK tile

    // cp.async mappings (1 A-chunk + 1 B-chunk of 16 B per thread)
    const int am  = tid >> 2;            // A row 0..63
    const int ak4 = (tid & 3) * 4;       // A k offset {0,4,8,12}
    const int bkr = tid >> 4;            // B k row 0..15
    const int bn4 = (tid & 15) * 4;      // B n offset

    const float* Abase = A + (size_t)(bm0 + am) * LDA + ak4;
    const float* Wbase = W + (size_t)bkr * H + bn0 + bn4;

    float c[2][4][4];
#pragma unroll
    for (int i = 0; i < 2; i++)
#pragma unroll
        for (int j = 0; j < 4; j++)
#pragma unroll
            for (int q = 0; q < 4; q++) c[i][j][q] = 0.0f;

    // prologue: preload stages 0..STAGES-2
#pragma unroll
    for (int s = 0; s < STAGES - 1; s++) {
        float* st = smem + s * STAGE_WORDS;
        cp16(st + am * A_STRIDE + ak4, Abase + s * BK);
        cp16(st + A_STAGE_WORDS + bkr * B_STRIDE + bn4, Wbase + (size_t)s * BK * H);
        asm volatile("cp.async.commit_group;\n" ::: "memory");
    }

    for (int it = 0; it < ITERS; it++) {
        asm volatile("cp.async.wait_group 1;\n" ::: "memory");
        __syncthreads();

        // issue load for iter it+STAGES-1 (or empty commit to keep count)
        int nit = it + STAGES - 1;
        if (nit < ITERS) {
            float* st = smem + (nit % STAGES) * STAGE_WORDS;
            cp16(st + am * A_STRIDE + ak4, Abase + nit * BK);
            cp16(st + A_STAGE_WORDS + bkr * B_STRIDE + bn4,
                 Wbase + (size_t)nit * BK * H);
        }
        asm volatile("cp.async.commit_group;\n" ::: "memory");

        const float* As = smem + (it % STAGES) * STAGE_WORDS;
        const float* Bs = As + A_STAGE_WORDS;

        uint32_t a[2][4], b[4][2];
#pragma unroll
        for (int mf = 0; mf < 2; mf++) {
            int m = wm0 + mf * 16 + mrow;
            a[mf][0] = __float_as_uint(As[m * A_STRIDE + kb + kq]);
            a[mf][1] = __float_as_uint(As[(m + 8) * A_STRIDE + kb + kq]);
            a[mf][2] = __float_as_uint(As[m * A_STRIDE + kb + kq + 4]);
            a[mf][3] = __float_as_uint(As[(m + 8) * A_STRIDE + kb + kq + 4]);
        }
#pragma unroll
        for (int nf = 0; nf < 4; nf++) {
            int n = wn0 + nf * 8 + mrow;
            b[nf][0] = __float_as_uint(Bs[(kb + kq) * B_STRIDE + n]);
            b[nf][1] = __float_as_uint(Bs[(kb + kq + 4) * B_STRIDE + n]);
        }
#pragma unroll
        for (int mf = 0; mf < 2; mf++)
#pragma unroll
            for (int nf = 0; nf < 4; nf++) {
                asm volatile(
                    "mma.sync.aligned.m16n8k8.row.col.f32.tf32.tf32.f32 "
                    "{%0,%1,%2,%3}, {%4,%5,%6,%7}, {%8,%9}, {%0,%1,%2,%3};"
                    : "+f"(c[mf][nf][0]), "+f"(c[mf][nf][1]),
                      "+f"(c[mf][nf][2]), "+f"(c[mf][nf][3])
                    : "r"(a[mf][0]), "r"(a[mf][1]), "r"(a[mf][2]), "r"(a[mf][3]),
                      "r"(b[nf][0]), "r"(b[nf][1]));
            }
    }

    // epilogue: cross-kgroup reduction through smem, + bias, store
    __syncthreads();
    if (kg == 1) {
        float* red = smem + wq * 1024;
        int i = 0;
#pragma unroll
        for (int mf = 0; mf < 2; mf++)
#pragma unroll
            for (int nf = 0; nf < 4; nf++)
#pragma unroll
                for (int q = 0; q < 4; q++) {
                    red[i * 32 + lane] = c[mf][nf][q];
                    i++;
                }
    }
    __syncthreads();
    if (kg == 0) {
        const float* red = smem + wq * 1024;
        int i = 0;
#pragma unroll
        for (int mf = 0; mf < 2; mf++)
#pragma unroll
            for (int nf = 0; nf < 4; nf++)
#pragma unroll
                for (int q = 0; q < 4; q++) {
                    c[mf][nf][q] += red[i * 32 + lane];
                    i++;
                }
#pragma unroll
        for (int mf = 0; mf < 2; mf++) {
            int m = bm0 + wm0 + mf * 16 + mrow;
#pragma unroll
            for (int nf = 0; nf < 4; nf++) {
                int n = bn0 + wn0 + nf * 8 + kq * 2;
                float2 bb = *(const float2*)(bias + n);
                float2 o0 = make_float2(c[mf][nf][0] + bb.x, c[mf][nf][1] + bb.y);
                float2 o1 = make_float2(c[mf][nf][2] + bb.x, c[mf][nf][3] + bb.y);
                *(float2*)&g_pred[(size_t)m * H + n] = o0;
                *(float2*)&g_pred[(size_t)(m + 8) * H + n] = o1;
            }
        }
    }
}

// ---------------------------------------------------------------------------
// Kernel B: per-group logits + log-softmax term (L2-gather bound).
// ---------------------------------------------------------------------------
__global__ __launch_bounds__(256) void loss_kernel(const float* __restrict__ emb,
                                                   const int* __restrict__ perm) {
    const int g    = blockIdx.x;
    const int tid  = threadIdx.x;
    const int warp = tid >> 5;
    const int lane = tid & 31;

    __shared__ float s_pred[H];
    __shared__ float s_logits[NLOG];
    __shared__ int   s_row[NLOG];

    s_pred[tid] = g_pred[(size_t)g * H + tid];
    if (tid < MNEG) {
        int p = perm[(size_t)g * MNEG + tid];
        s_row[tid + 1] = p + ((p >= 4 * g) ? 4 : 0);
    }
    if (tid == MNEG) s_row[0] = 4 * g + 3;
    __syncthreads();

    const float4* p4 = (const float4*)s_pred;
    const float4 pa = p4[lane];
    const float4 pb = p4[lane + 32];

    for (int j = warp; j < NLOG; j += 8) {
        const float4* e4 = (const float4*)(emb + (size_t)s_row[j] * H);
        float4 ea = e4[lane];
        float4 eb = e4[lane + 32];
        float s = ea.x * pa.x + ea.y * pa.y + ea.z * pa.z + ea.w * pa.w
                + eb.x * pb.x + eb.y * pb.y + eb.z * pb.z + eb.w * pb.w;
#pragma unroll
        for (int off = 16; off > 0; off >>= 1)
            s += __shfl_down_sync(0xffffffffu, s, off);
        if (lane == 0) s_logits[j] = s;
    }
    __syncthreads();

    if (warp == 0) {
        float v0 = s_logits[lane];
        float v1 = s_logits[lane + 32];
        float v2 = (lane == 0) ? s_logits[64] : -INFINITY;
        float m = fmaxf(fmaxf(v0, v1), v2);
#pragma unroll
        for (int off = 16; off > 0; off >>= 1)
            m = fmaxf(m, __shfl_xor_sync(0xffffffffu, m, off));
        float s = expf(v0 - m) + expf(v1 - m) + ((lane == 0) ? expf(v2 - m) : 0.0f);
#pragma unroll
        for (int off = 16; off > 0; off >>= 1)
            s += __shfl_xor_sync(0xffffffffu, s, off);
        float lse = m + logf(s);
        if (lane == 0) g_terms[g] = lse - s_logits[0];
    }
}

// ---------------------------------------------------------------------------
// Kernel C: deterministic mean
// ---------------------------------------------------------------------------
__global__ __launch_bounds__(256) void reduce_kernel(float* __restrict__ out) {
    __shared__ float s[256];
    float v = 0.0f;
    for (int i = threadIdx.x; i < NG; i += 256)
        v += g_terms[i];
    s[threadIdx.x] = v;
    __syncthreads();
    for (int st = 128; st > 0; st >>= 1) {
        if (threadIdx.x < st) s[threadIdx.x] += s[threadIdx.x + st];
        __syncthreads();
    }
    if (threadIdx.x == 0) out[0] = s[0] / (float)NG;
}

// ---------------------------------------------------------------------------
extern "C" void kernel_launch(void* const* d_in, const int* in_sizes, int n_in,
                              void* d_out, int out_size) {
    const float* emb  = (const float*)d_in[0];   // (16384, 256) f32
    const float* W    = (const float*)d_in[1];   // (768, 256)   f32
    const float* bias = (const float*)d_in[2];   // (256,)       f32
    // d_in[3] = target (analytic, unused)
    const int* perm   = (const int*)d_in[4];     // (4096, 64)   int32

    dim3 ggrid(H / BN, NG / BM);   // (4, 64)
    gemm_tc<<<ggrid, 256>>>(emb, W, bias);
    loss_kernel<<<NG, 256>>>(emb, perm);
    reduce_kernel<<<1, 256>>>((float*)d_out);
}